// round 1
// baseline (speedup 1.0000x reference)
#include <cuda_runtime.h>
#include <math.h>

// Problem constants
#define NH    10
#define BSZ   16384
#define NF    4
#define DD1   2048
#define DD2   2048      // D21 == D22
#define BM    128
#define BN    64
#define KT    16
#define NTILES_PER (DD2/BN)   // 32

// Scratch for per-head partial projections: x31 pre-bias, x32 pre-sigmoid.
// (H, B, 2) each, fp32. Static device globals (no allocation allowed).
__device__ float g_s31[NH * BSZ * 2];
__device__ float g_s32[NH * BSZ * 2];

// Fused GEMM: computes relu(h1 @ W2x + b2x) tile and immediately projects it
// through W3x[:,0:2], accumulating into g_s31 / g_s32 via atomics.
// h1 = relu(x @ W1[h] + b1[h]) is recomputed on the fly (F=4, nearly free).
__global__ __launch_bounds__(256, 3) void abnet_gemm_kernel(
    const float* __restrict__ x,
    const float* __restrict__ W1,
    const float* __restrict__ b1,
    const float* __restrict__ W21,
    const float* __restrict__ b21,
    const float* __restrict__ W22,
    const float* __restrict__ b22,
    const float* __restrict__ W31,
    const float* __restrict__ W32)
{
    const int mTile = blockIdx.x;
    const int nTile = blockIdx.y;
    const int h     = blockIdx.z;

    const bool second = (nTile >= NTILES_PER);
    const int  e0 = (second ? nTile - NTILES_PER : nTile) * BN;
    const float* __restrict__ Wb   = second ? W22 : W21;
    const float* __restrict__ bias = (second ? b22 : b21) + h * DD2;
    const float* __restrict__ Wp   = (second ? W32 : W31) + (size_t)h * DD2 * 2;
    float* __restrict__ sc         = second ? g_s32 : g_s31;

    __shared__ float xs[BM][4];
    __shared__ float As[KT][BM + 4];   // h1 tile, k-major (transposed)
    __shared__ float Bs[KT][BN + 4];   // weight tile

    const int t  = threadIdx.x;
    const int tx = t & 15;       // n direction (4 cols each)
    const int ty = t >> 4;       // m direction (8 rows each)
    const int m0 = mTile * BM;

    // Load x tile (128 rows x 4 feats)
    if (t < BM) {
        float4 v = *(const float4*)(x + (size_t)(m0 + t) * 4);
        xs[t][0] = v.x; xs[t][1] = v.y; xs[t][2] = v.z; xs[t][3] = v.w;
    }
    __syncthreads();

    float acc[8][4];
    #pragma unroll
    for (int i = 0; i < 8; i++)
        #pragma unroll
        for (int j = 0; j < 4; j++) acc[i][j] = 0.f;

    const float* __restrict__ W1h = W1 + (size_t)h * NF * DD1;
    const float* __restrict__ b1h = b1 + (size_t)h * DD1;
    const float* __restrict__ Wbh = Wb + (size_t)h * DD1 * DD2;

    const int kk = t & 15;   // which k this thread computes h1 for
    const int mg = t >> 4;   // which group of 8 m-rows

    for (int k0 = 0; k0 < DD1; k0 += KT) {
        // --- Load weight tile (KT x BN), coalesced float4 ---
        {
            const int row = t >> 4;      // 0..15
            const int c4  = t & 15;      // 0..15
            float4 bv = *(const float4*)(Wbh + (size_t)(k0 + row) * DD2 + e0 + c4 * 4);
            *(float4*)&Bs[row][c4 * 4] = bv;
        }
        // --- Recompute h1 tile (k-major): h1[k][m] = relu(x[m,:]·W1[:,k] + b1[k]) ---
        {
            const float w0 = W1h[0 * DD1 + k0 + kk];
            const float w1 = W1h[1 * DD1 + k0 + kk];
            const float w2 = W1h[2 * DD1 + k0 + kk];
            const float w3 = W1h[3 * DD1 + k0 + kk];
            const float bb = b1h[k0 + kk];
            #pragma unroll
            for (int i = 0; i < 8; i++) {
                const int m = mg * 8 + i;
                float v = fmaf(xs[m][3], w3, bb);
                v = fmaf(xs[m][2], w2, v);
                v = fmaf(xs[m][1], w1, v);
                v = fmaf(xs[m][0], w0, v);
                As[kk][m] = fmaxf(v, 0.f);
            }
        }
        __syncthreads();

        // --- 8x4 outer-product MAC loop ---
        #pragma unroll
        for (int k = 0; k < KT; k++) {
            float a[8], bv[4];
            *(float4*)(a)     = *(const float4*)&As[k][ty * 8];
            *(float4*)(a + 4) = *(const float4*)&As[k][ty * 8 + 4];
            *(float4*)(bv)    = *(const float4*)&Bs[k][tx * 4];
            #pragma unroll
            for (int i = 0; i < 8; i++)
                #pragma unroll
                for (int j = 0; j < 4; j++)
                    acc[i][j] = fmaf(a[i], bv[j], acc[i][j]);
        }
        __syncthreads();
    }

    // --- Epilogue: relu(acc + bias), project to C=2, reduce over n ---
    float p[8][2];
    #pragma unroll
    for (int i = 0; i < 8; i++) { p[i][0] = 0.f; p[i][1] = 0.f; }

    #pragma unroll
    for (int j = 0; j < 4; j++) {
        const int e = e0 + tx * 4 + j;
        const float bj = bias[e];
        const float w0 = Wp[e * 2 + 0];
        const float w1 = Wp[e * 2 + 1];
        #pragma unroll
        for (int i = 0; i < 8; i++) {
            const float v = fmaxf(acc[i][j] + bj, 0.f);
            p[i][0] = fmaf(v, w0, p[i][0]);
            p[i][1] = fmaf(v, w1, p[i][1]);
        }
    }

    // Reduce across the 16 tx lanes (same ty => same m rows) via xor-shuffle.
    #pragma unroll
    for (int i = 0; i < 8; i++) {
        #pragma unroll
        for (int c = 0; c < 2; c++) {
            float v = p[i][c];
            v += __shfl_xor_sync(0xffffffffu, v, 1, 16);
            v += __shfl_xor_sync(0xffffffffu, v, 2, 16);
            v += __shfl_xor_sync(0xffffffffu, v, 4, 16);
            v += __shfl_xor_sync(0xffffffffu, v, 8, 16);
            p[i][c] = v;
        }
    }
    if (tx == 0) {
        #pragma unroll
        for (int i = 0; i < 8; i++) {
            const size_t m = (size_t)m0 + ty * 8 + i;
            atomicAdd(&sc[((size_t)h * BSZ + m) * 2 + 0], p[i][0]);
            atomicAdd(&sc[((size_t)h * BSZ + m) * 2 + 1], p[i][1]);
        }
    }
}

// Final: CBF-QP per (h,b), softmax-weighted head mix.
__global__ __launch_bounds__(256) void abnet_final_kernel(
    const float* __restrict__ x,
    const float* __restrict__ b31,
    const float* __restrict__ b32,
    const float* __restrict__ wt,
    const float* __restrict__ mean,
    const float* __restrict__ stdv,
    float* __restrict__ out)
{
    const int b = blockIdx.x * blockDim.x + threadIdx.x;
    if (b >= BSZ) return;

    // softmax(wt) over 10 heads
    float wv[NH];
    float mx = -1e30f;
    #pragma unroll
    for (int h = 0; h < NH; h++) { wv[h] = wt[h]; mx = fmaxf(mx, wv[h]); }
    float s = 0.f;
    #pragma unroll
    for (int h = 0; h < NH; h++) { wv[h] = expf(wv[h] - mx); s += wv[h]; }
    const float inv = 1.f / s;

    const float4 xv = *(const float4*)(x + (size_t)b * 4);
    const float px = xv.x * stdv[0] + mean[0];
    const float py = xv.y * stdv[1] + mean[1];
    const float th = xv.z * stdv[2] + mean[2];
    const float v  = xv.w * stdv[3] + mean[3];

    const float dx = px - 40.0f;
    const float dy = py - 15.0f;
    const float st = sinf(th);
    const float ct = cosf(th);
    const float barrier = dx * dx + dy * dy - 36.0f;   // RADIUS^2 = 36
    const float bdot = 2.f * dx * v * ct + 2.f * dy * v * st;
    const float Lf2b = 2.f * v * v;
    const float L1 = -2.f * dx * v * st + 2.f * dy * v * ct;
    const float L2 =  2.f * dx * ct + 2.f * dy * st;
    const float G0 = -L1;
    const float G1 = -L2;
    const float GG = G0 * G0 + G1 * G1;

    float o0 = 0.f, o1 = 0.f;
    #pragma unroll
    for (int h = 0; h < NH; h++) {
        const size_t base = ((size_t)h * BSZ + b) * 2;
        const float x310 = g_s31[base + 0] + b31[h * 2 + 0];
        const float x311 = g_s31[base + 1] + b31[h * 2 + 1];
        const float p0   = g_s32[base + 0] + b32[h * 2 + 0];
        const float p1   = g_s32[base + 1] + b32[h * 2 + 1];
        const float x320 = 4.f / (1.f + expf(-p0));
        const float x321 = 4.f / (1.f + expf(-p1));
        const float hr  = Lf2b + (x320 + x321) * bdot + x320 * x321 * barrier;
        const float Gu  = G0 * x310 + G1 * x311;
        const float lam = fmaxf(Gu - hr, 0.f) / GG;
        const float wh  = wv[h] * inv;
        o0 += wh * (x310 - lam * G0);
        o1 += wh * (x311 - lam * G1);
    }
    out[(size_t)b * 2 + 0] = o0;
    out[(size_t)b * 2 + 1] = o1;
}

extern "C" void kernel_launch(void* const* d_in, const int* in_sizes, int n_in,
                              void* d_out, int out_size)
{
    const float* x    = (const float*)d_in[0];
    const float* W1   = (const float*)d_in[1];
    const float* b1   = (const float*)d_in[2];
    const float* W21  = (const float*)d_in[3];
    const float* b21  = (const float*)d_in[4];
    const float* W22  = (const float*)d_in[5];
    const float* b22  = (const float*)d_in[6];
    const float* W31  = (const float*)d_in[7];
    const float* b31  = (const float*)d_in[8];
    const float* W32  = (const float*)d_in[9];
    const float* b32  = (const float*)d_in[10];
    const float* wt   = (const float*)d_in[11];
    const float* mean = (const float*)d_in[12];
    const float* stdv = (const float*)d_in[13];
    float* out = (float*)d_out;

    static float* s31_addr = nullptr;
    static float* s32_addr = nullptr;
    if (!s31_addr) {
        cudaGetSymbolAddress((void**)&s31_addr, g_s31);
        cudaGetSymbolAddress((void**)&s32_addr, g_s32);
    }

    // Zero the partial-sum scratch (graph-capturable async memset).
    cudaMemsetAsync(s31_addr, 0, (size_t)NH * BSZ * 2 * sizeof(float), 0);
    cudaMemsetAsync(s32_addr, 0, (size_t)NH * BSZ * 2 * sizeof(float), 0);

    // Grid: m fastest (x), so concurrent CTAs share the same weight n-slice in L2.
    dim3 grid(BSZ / BM, 2 * NTILES_PER, NH);
    abnet_gemm_kernel<<<grid, 256>>>(x, W1, b1, W21, b21, W22, b22, W31, W32);

    abnet_final_kernel<<<BSZ / 256, 256>>>(x, b31, b32, wt, mean, stdv, out);
}

// round 3
// speedup vs baseline: 9.6626x; 9.6626x over previous
#include <cuda_runtime.h>
#include <cuda_fp16.h>
#include <math.h>
#include <stdint.h>

// ---------------- problem constants ----------------
#define NH   10
#define BSZ  16384
#define DD   2048      // D1 == D21 == D22
#define BM   128
#define BN   128
#define BK   64
#define NS   (DD/BK)   // 32 k-stages
#define STAGE_BYTES 32768   // A 16KB + B 16KB per stage
#define SMEM_TOTAL  (3 * STAGE_BYTES)

// ---------------- device scratch (no allocation allowed) ----------------
__device__ __align__(16) __half g_H1  [(size_t)NH * BSZ * DD];   // h1 fp16, [h][m][k]
__device__ __align__(16) __half g_W21T[(size_t)NH * DD * DD];    // W21^T fp16, [h][e][k]
__device__ __align__(16) __half g_W22T[(size_t)NH * DD * DD];    // W22^T fp16, [h][e][k]
__device__ float g_s31[NH * BSZ * 2];
__device__ float g_s32[NH * BSZ * 2];

// ---------------- helpers ----------------
__device__ __forceinline__ uint32_t smem_u32(const void* p) {
    uint32_t a;
    asm("{ .reg .u64 t; cvta.to.shared.u64 t, %1; cvt.u32.u64 %0, t; }" : "=r"(a) : "l"(p));
    return a;
}
__device__ __forceinline__ void cp16(uint32_t saddr, const void* g) {
    asm volatile("cp.async.cg.shared.global [%0], [%1], 16;" :: "r"(saddr), "l"(g));
}
__device__ __forceinline__ void cp_commit() { asm volatile("cp.async.commit_group;" ::: "memory"); }
__device__ __forceinline__ void cp_wait1()  { asm volatile("cp.async.wait_group 1;" ::: "memory"); }
__device__ __forceinline__ void cp_wait0()  { asm volatile("cp.async.wait_group 0;" ::: "memory"); }
__device__ __forceinline__ void ldsm4(uint32_t* r, uint32_t addr) {
    asm volatile("ldmatrix.sync.aligned.m8n8.x4.shared.b16 {%0,%1,%2,%3}, [%4];"
                 : "=r"(r[0]), "=r"(r[1]), "=r"(r[2]), "=r"(r[3]) : "r"(addr));
}
__device__ __forceinline__ void mma16816(float* c, const uint32_t* a, const uint32_t* b) {
    asm volatile(
        "mma.sync.aligned.m16n8k16.row.col.f32.f16.f16.f32 "
        "{%0,%1,%2,%3}, {%4,%5,%6,%7}, {%8,%9}, {%0,%1,%2,%3};"
        : "+f"(c[0]), "+f"(c[1]), "+f"(c[2]), "+f"(c[3])
        : "r"(a[0]), "r"(a[1]), "r"(a[2]), "r"(a[3]), "r"(b[0]), "r"(b[1]));
}
#define SW128(off) ((off) ^ (((off) >> 3) & 0x70))

// ---------------- kernel 1: H1 = relu(x @ W1 + b1) in fp16 ----------------
__global__ __launch_bounds__(256) void h1_kernel(
    const float* __restrict__ x, const float* __restrict__ W1, const float* __restrict__ b1)
{
    const size_t idx = (size_t)blockIdx.x * 256 + threadIdx.x;
    const int k8 = (int)(idx & 255);          // DD/8 = 256
    const size_t hm = idx >> 8;
    const int m = (int)(hm & (BSZ - 1));
    const int h = (int)(hm >> 14);

    const float4 xv = *(const float4*)(x + (size_t)m * 4);
    const float* W1h = W1 + ((size_t)h * 4) * DD + k8 * 8;
    const float* b1h = b1 + (size_t)h * DD + k8 * 8;

    float r[8];
    {
        float4 ba = *(const float4*)(b1h);
        float4 bb = *(const float4*)(b1h + 4);
        r[0]=ba.x; r[1]=ba.y; r[2]=ba.z; r[3]=ba.w;
        r[4]=bb.x; r[5]=bb.y; r[6]=bb.z; r[7]=bb.w;
    }
    const float xf[4] = {xv.x, xv.y, xv.z, xv.w};
    #pragma unroll
    for (int f = 0; f < 4; f++) {
        float4 wa = *(const float4*)(W1h + (size_t)f * DD);
        float4 wb = *(const float4*)(W1h + (size_t)f * DD + 4);
        r[0]=fmaf(xf[f], wa.x, r[0]); r[1]=fmaf(xf[f], wa.y, r[1]);
        r[2]=fmaf(xf[f], wa.z, r[2]); r[3]=fmaf(xf[f], wa.w, r[3]);
        r[4]=fmaf(xf[f], wb.x, r[4]); r[5]=fmaf(xf[f], wb.y, r[5]);
        r[6]=fmaf(xf[f], wb.z, r[6]); r[7]=fmaf(xf[f], wb.w, r[7]);
    }
    __half2 o[4];
    #pragma unroll
    for (int j = 0; j < 4; j++)
        o[j] = __floats2half2_rn(fmaxf(r[2*j], 0.f), fmaxf(r[2*j+1], 0.f));
    *(uint4*)(g_H1 + ((size_t)h * BSZ + m) * DD + (size_t)k8 * 8) = *(uint4*)o;
}

// ---------------- kernel 2: W2x^T fp16 transpose-convert ----------------
__global__ __launch_bounds__(256) void wt_kernel(
    const float* __restrict__ W21, const float* __restrict__ W22)
{
    __shared__ float ts[32][33];
    const int hb = blockIdx.z;
    const int h = hb >> 1;
    const float* W = (hb & 1) ? W22 : W21;
    __half* WT = (hb & 1) ? g_W22T : g_W21T;
    W  += (size_t)h * DD * DD;
    WT += (size_t)h * DD * DD;
    const int k0 = blockIdx.y * 32, e0 = blockIdx.x * 32;
    const int tx = threadIdx.x & 31, ty = threadIdx.x >> 5;   // 32 x 8
    #pragma unroll
    for (int r = 0; r < 4; r++)
        ts[ty + r*8][tx] = W[(size_t)(k0 + ty + r*8) * DD + e0 + tx];
    __syncthreads();
    #pragma unroll
    for (int r = 0; r < 4; r++)
        WT[(size_t)(e0 + ty + r*8) * DD + k0 + tx] = __float2half(ts[tx][ty + r*8]);
}

// ---------------- kernel 3: HMMA GEMM + fused projection ----------------
// C[m,e] = H1[h,m,:] @ W2T[h,e,:]^T ; v = relu(C + b2[e]); scratch += v @ W3[:,0:2]
__global__ __launch_bounds__(256, 2) void gemm_kernel(
    const float* __restrict__ b21, const float* __restrict__ b22,
    const float* __restrict__ W31, const float* __restrict__ W32)
{
    extern __shared__ char smem[];
    const uint32_t sbase = smem_u32(smem);
    const int t = threadIdx.x, warp = t >> 5, lane = t & 31;
    const int wm = warp >> 2, wn = warp & 3;        // 2 x 4 warp grid

    const int m0 = blockIdx.x * BM, e0 = blockIdx.y * BN;
    const int hb = blockIdx.z, h = hb >> 1, br = hb & 1;

    const __half* __restrict__ A  = g_H1 + ((size_t)h * BSZ + m0) * DD;
    const __half* __restrict__ Bp = (br ? g_W22T : g_W21T) + ((size_t)h * DD + e0) * DD;
    const float*  __restrict__ bias = (br ? b22 : b21) + (size_t)h * DD;
    const float*  __restrict__ Wp   = (br ? W32 : W31) + (size_t)h * DD * 2;
    float* __restrict__ sc = br ? g_s32 : g_s31;

    float acc[4][4][4];
    #pragma unroll
    for (int i = 0; i < 4; i++)
        #pragma unroll
        for (int j = 0; j < 4; j++)
            #pragma unroll
            for (int q = 0; q < 4; q++) acc[i][j][q] = 0.f;

    // per-thread cp.async coords: 4 chunks each for A and B
    const int lrow[4] = { (0*256 + t) >> 3, (1*256 + t) >> 3, (2*256 + t) >> 3, (3*256 + t) >> 3 };
    const int lcol = (t & 7) * 8;   // halves; same low bits for all 4 chunks

    #define ISSUE(s) do {                                                           \
        const int k0_ = (s) * BK;                                                   \
        const uint32_t sb_ = sbase + ((s) % 3) * STAGE_BYTES;                       \
        _Pragma("unroll")                                                           \
        for (int i_ = 0; i_ < 4; i_++) {                                            \
            const int row_ = lrow[i_];                                              \
            const uint32_t so_ = SW128((uint32_t)(row_ * 128 + lcol * 2));          \
            cp16(sb_ + so_,          A  + (size_t)row_ * DD + k0_ + lcol);          \
            cp16(sb_ + 16384 + so_,  Bp + (size_t)row_ * DD + k0_ + lcol);          \
        }                                                                           \
        cp_commit();                                                                \
    } while (0)

    ISSUE(0);
    ISSUE(1);

    for (int s = 0; s < NS; s++) {
        if (s == NS - 1) cp_wait0(); else cp_wait1();
        __syncthreads();
        if (s + 2 < NS) ISSUE(s + 2);

        const uint32_t sb = sbase + (s % 3) * STAGE_BYTES;
        #pragma unroll
        for (int ks = 0; ks < 4; ks++) {
            const int kb = ks * 16;
            uint32_t a[4][4], b[2][4];
            #pragma unroll
            for (int mi = 0; mi < 4; mi++) {
                const int row = wm * 64 + mi * 16 + (lane & 15);
                const int kc  = kb + (lane >> 4) * 8;
                ldsm4(a[mi], sb + SW128((uint32_t)(row * 128 + kc * 2)));
            }
            #pragma unroll
            for (int g = 0; g < 2; g++) {
                const int nrow = wn * 32 + g * 16 + (lane & 7) + ((lane >> 4) << 3);
                const int kc   = kb + ((lane >> 3) & 1) * 8;
                ldsm4(b[g], sb + 16384 + SW128((uint32_t)(nrow * 128 + kc * 2)));
            }
            #pragma unroll
            for (int mi = 0; mi < 4; mi++)
                #pragma unroll
                for (int ni = 0; ni < 4; ni++)
                    mma16816(acc[mi][ni], a[mi], &b[ni >> 1][(ni & 1) * 2]);
        }
    }
    __syncthreads();

    // ---- epilogue: bias + relu + project to C=2, reduce ----
    float* red = (float*)smem;      // 128 rows x 2 chans
    red[t] = 0.f;                   // t < 256
    __syncthreads();

    float be0[4], be1[4], w00[4], w01[4], w10[4], w11[4];
    #pragma unroll
    for (int ni = 0; ni < 4; ni++) {
        const int e = e0 + wn * 32 + ni * 8 + 2 * (lane & 3);
        const float2 bb = *(const float2*)(bias + e);
        be0[ni] = bb.x; be1[ni] = bb.y;
        const float4 ww = *(const float4*)(Wp + 2 * e);
        w00[ni] = ww.x; w01[ni] = ww.y; w10[ni] = ww.z; w11[ni] = ww.w;
    }
    #pragma unroll
    for (int mi = 0; mi < 4; mi++) {
        float p00 = 0.f, p01 = 0.f, p10 = 0.f, p11 = 0.f;
        #pragma unroll
        for (int ni = 0; ni < 4; ni++) {
            const float v0 = fmaxf(acc[mi][ni][0] + be0[ni], 0.f);
            const float v1 = fmaxf(acc[mi][ni][1] + be1[ni], 0.f);
            const float v2 = fmaxf(acc[mi][ni][2] + be0[ni], 0.f);
            const float v3 = fmaxf(acc[mi][ni][3] + be1[ni], 0.f);
            p00 = fmaf(v0, w00[ni], fmaf(v1, w10[ni], p00));
            p01 = fmaf(v0, w01[ni], fmaf(v1, w11[ni], p01));
            p10 = fmaf(v2, w00[ni], fmaf(v3, w10[ni], p10));
            p11 = fmaf(v2, w01[ni], fmaf(v3, w11[ni], p11));
        }
        // reduce across the 4 lanes of each quad (same rows, different cols)
        #pragma unroll
        for (int d = 1; d <= 2; d <<= 1) {
            p00 += __shfl_xor_sync(0xffffffffu, p00, d);
            p01 += __shfl_xor_sync(0xffffffffu, p01, d);
            p10 += __shfl_xor_sync(0xffffffffu, p10, d);
            p11 += __shfl_xor_sync(0xffffffffu, p11, d);
        }
        if ((lane & 3) == 0) {
            const int r0 = wm * 64 + mi * 16 + (lane >> 2);
            atomicAdd(&red[r0 * 2 + 0], p00);
            atomicAdd(&red[r0 * 2 + 1], p01);
            atomicAdd(&red[(r0 + 8) * 2 + 0], p10);
            atomicAdd(&red[(r0 + 8) * 2 + 1], p11);
        }
    }
    __syncthreads();
    atomicAdd(&sc[((size_t)h * BSZ + m0 + (t >> 1)) * 2 + (t & 1)], red[t]);
}

// ---------------- kernel 4: CBF-QP + softmax head mix ----------------
__global__ __launch_bounds__(256) void abnet_final_kernel(
    const float* __restrict__ x,
    const float* __restrict__ b31, const float* __restrict__ b32,
    const float* __restrict__ wt,
    const float* __restrict__ mean, const float* __restrict__ stdv,
    float* __restrict__ out)
{
    const int b = blockIdx.x * blockDim.x + threadIdx.x;
    if (b >= BSZ) return;

    float wv[NH];
    float mx = -1e30f;
    #pragma unroll
    for (int h = 0; h < NH; h++) { wv[h] = wt[h]; mx = fmaxf(mx, wv[h]); }
    float s = 0.f;
    #pragma unroll
    for (int h = 0; h < NH; h++) { wv[h] = expf(wv[h] - mx); s += wv[h]; }
    const float inv = 1.f / s;

    const float4 xv = *(const float4*)(x + (size_t)b * 4);
    const float px = xv.x * stdv[0] + mean[0];
    const float py = xv.y * stdv[1] + mean[1];
    const float th = xv.z * stdv[2] + mean[2];
    const float v  = xv.w * stdv[3] + mean[3];

    const float dx = px - 40.0f;
    const float dy = py - 15.0f;
    const float st = sinf(th);
    const float ct = cosf(th);
    const float barrier = dx * dx + dy * dy - 36.0f;
    const float bdot = 2.f * dx * v * ct + 2.f * dy * v * st;
    const float Lf2b = 2.f * v * v;
    const float G0 = 2.f * dx * v * st - 2.f * dy * v * ct;   // -LgLfbu1
    const float G1 = -2.f * dx * ct - 2.f * dy * st;          // -LgLfbu2
    const float GG = G0 * G0 + G1 * G1;

    float o0 = 0.f, o1 = 0.f;
    #pragma unroll
    for (int h = 0; h < NH; h++) {
        const size_t base = ((size_t)h * BSZ + b) * 2;
        const float x310 = g_s31[base + 0] + b31[h * 2 + 0];
        const float x311 = g_s31[base + 1] + b31[h * 2 + 1];
        const float p0   = g_s32[base + 0] + b32[h * 2 + 0];
        const float p1   = g_s32[base + 1] + b32[h * 2 + 1];
        const float x320 = 4.f / (1.f + expf(-p0));
        const float x321 = 4.f / (1.f + expf(-p1));
        const float hr  = Lf2b + (x320 + x321) * bdot + x320 * x321 * barrier;
        const float Gu  = G0 * x310 + G1 * x311;
        const float lam = fmaxf(Gu - hr, 0.f) / GG;
        const float wh  = wv[h] * inv;
        o0 += wh * (x310 - lam * G0);
        o1 += wh * (x311 - lam * G1);
    }
    out[(size_t)b * 2 + 0] = o0;
    out[(size_t)b * 2 + 1] = o1;
}

// ---------------- launch ----------------
extern "C" void kernel_launch(void* const* d_in, const int* in_sizes, int n_in,
                              void* d_out, int out_size)
{
    const float* x    = (const float*)d_in[0];
    const float* W1   = (const float*)d_in[1];
    const float* b1   = (const float*)d_in[2];
    const float* W21  = (const float*)d_in[3];
    const float* b21  = (const float*)d_in[4];
    const float* W22  = (const float*)d_in[5];
    const float* b22  = (const float*)d_in[6];
    const float* W31  = (const float*)d_in[7];
    const float* b31  = (const float*)d_in[8];
    const float* W32  = (const float*)d_in[9];
    const float* b32  = (const float*)d_in[10];
    const float* wt   = (const float*)d_in[11];
    const float* mean = (const float*)d_in[12];
    const float* stdv = (const float*)d_in[13];
    float* out = (float*)d_out;

    static float* s31_addr = nullptr;
    static float* s32_addr = nullptr;
    if (!s31_addr) {
        cudaGetSymbolAddress((void**)&s31_addr, g_s31);
        cudaGetSymbolAddress((void**)&s32_addr, g_s32);
        cudaFuncSetAttribute(gemm_kernel, cudaFuncAttributeMaxDynamicSharedMemorySize, SMEM_TOTAL);
    }

    cudaMemsetAsync(s31_addr, 0, (size_t)NH * BSZ * 2 * sizeof(float), 0);
    cudaMemsetAsync(s32_addr, 0, (size_t)NH * BSZ * 2 * sizeof(float), 0);

    h1_kernel<<<(NH * BSZ * (DD / 8)) / 256, 256>>>(x, W1, b1);

    dim3 tg(DD / 32, DD / 32, NH * 2);
    wt_kernel<<<tg, 256>>>(W21, W22);

    dim3 grid(BSZ / BM, DD / BN, NH * 2);
    gemm_kernel<<<grid, 256, SMEM_TOTAL>>>(b21, b22, W31, W32);

    abnet_final_kernel<<<BSZ / 256, 256>>>(x, b31, b32, wt, mean, stdv, out);
}